// round 4
// baseline (speedup 1.0000x reference)
#include <cuda_runtime.h>
#include <cuda_bf16.h>

#define NMAX 100000
#define F 256
#define H 32
#define C 40

// Scratch (allocation-free rule: __device__ globals)
__device__ __align__(16) float g_norm_src[NMAX];        // deg accum -> rsqrt in place
__device__ __align__(16) float g_norm_dst[NMAX];
__device__ __align__(16) float g_h1[NMAX * H];          // (x*ns) @ W1
__device__ __align__(16) float g_agg1[NMAX * H];        // scatter target layer 1
__device__ __align__(16) float g_h2[NMAX * C];          // (relu(agg1*nd+b1)*ns) @ W2

// ---------------------------------------------------------------- zero
__global__ void k_zero(float* __restrict__ out, int N) {
    int i = blockIdx.x * blockDim.x + threadIdx.x;
    int stride = gridDim.x * blockDim.x;
    for (int t = i; t < N * C; t += stride) {
        out[t] = 0.f;
        if (t < N * H) g_agg1[t] = 0.f;
        if (t < N) { g_norm_src[t] = 0.f; g_norm_dst[t] = 0.f; }
    }
}

// ---------------------------------------------------------------- degrees
__global__ void k_deg(const int* __restrict__ src, const int* __restrict__ dst, int E) {
    int i = blockIdx.x * blockDim.x + threadIdx.x;
    if (i >= E) return;
    atomicAdd(&g_norm_src[src[i]], 1.0f);
    atomicAdd(&g_norm_dst[dst[i]], 1.0f);
}

__global__ void k_norm(int N) {
    int i = blockIdx.x * blockDim.x + threadIdx.x;
    if (i >= N) return;
    g_norm_src[i] = rsqrtf(g_norm_src[i]);   // self-loops guarantee deg >= 1
    g_norm_dst[i] = rsqrtf(g_norm_dst[i]);
}

// ---------------------------------------------------------------- GEMM1: h1 = (x * norm_src) @ W1
// 32 rows per block, 256 threads. W1 [256x32] in smem (32KB), X tile [32x32] staged.
__global__ void k_gemm1(const float* __restrict__ x, const float* __restrict__ W1, int N) {
    __shared__ __align__(16) float Ws[F * H];     // 32 KB
    __shared__ __align__(16) float Xs[32 * 32];   // 4 KB
    const int tid = threadIdx.x;
    const int lane = tid & 31;
    const int w = tid >> 5;          // 0..7
    const int row0 = blockIdx.x * 32;

    for (int i = tid; i < F * H; i += 256) Ws[i] = W1[i];

    float acc[4] = {0.f, 0.f, 0.f, 0.f};

    for (int kb = 0; kb < F; kb += 32) {
        __syncthreads();
        #pragma unroll
        for (int i = tid; i < 32 * 32; i += 256) {
            int r = i >> 5, c = i & 31;
            int row = row0 + r;
            Xs[i] = (row < N) ? x[row * F + kb + c] : 0.f;
        }
        __syncthreads();
        #pragma unroll
        for (int k = 0; k < 32; k += 4) {
            float wv0 = Ws[(kb + k + 0) * H + lane];
            float wv1 = Ws[(kb + k + 1) * H + lane];
            float wv2 = Ws[(kb + k + 2) * H + lane];
            float wv3 = Ws[(kb + k + 3) * H + lane];
            #pragma unroll
            for (int r = 0; r < 4; r++) {
                float4 xv = *(const float4*)&Xs[(w * 4 + r) * 32 + k];
                acc[r] += xv.x * wv0 + xv.y * wv1 + xv.z * wv2 + xv.w * wv3;
            }
        }
    }
    #pragma unroll
    for (int r = 0; r < 4; r++) {
        int row = row0 + w * 4 + r;
        if (row < N) g_h1[row * H + lane] = acc[r] * g_norm_src[row];
    }
}

// ---------------------------------------------------------------- Aggregate layer 1
// 8 lanes per edge, each lane one float4 chunk: coalesced 128B gather + contiguous vec4 REDs.
__global__ void k_agg1(const int* __restrict__ src, const int* __restrict__ dst, int E) {
    int gid = blockIdx.x * blockDim.x + threadIdx.x;
    int e = gid >> 3;
    if (e >= E) return;
    int c = (gid & 7) * 4;
    int s = src[e], d = dst[e];
    float4 v = *(const float4*)&g_h1[s * H + c];
    float* p = &g_agg1[d * H + c];
    asm volatile("red.global.add.v4.f32 [%0], {%1,%2,%3,%4};"
                 :: "l"(p), "f"(v.x), "f"(v.y), "f"(v.z), "f"(v.w) : "memory");
}

// ---------------------------------------------------------------- GEMM2 (fused epilogue-1):
// x1 = relu(agg1 * norm_dst + b1);  h2 = (x1 * norm_src) @ W2   [32x40]
__global__ void k_gemm2(const float* __restrict__ W2, const float* __restrict__ b1, int N) {
    __shared__ __align__(16) float Ws[H * C];     // 5 KB
    __shared__ __align__(16) float Xs[32 * H];    // 4 KB
    const int tid = threadIdx.x;
    const int row0 = blockIdx.x * 32;

    for (int i = tid; i < H * C; i += 256) Ws[i] = W2[i];
    for (int i = tid; i < 32 * H; i += 256) {
        int r = i >> 5, c = i & 31;
        int row = row0 + r;
        float v = 0.f;
        if (row < N)
            v = fmaxf(fmaf(g_agg1[row * H + c], g_norm_dst[row], b1[c]), 0.f);
        Xs[i] = v;
    }
    __syncthreads();
    for (int i = tid; i < 32 * C; i += 256) {
        int r = i / C, j = i - r * C;
        float acc = 0.f;
        #pragma unroll
        for (int k = 0; k < H; k++) acc += Xs[r * H + k] * Ws[k * C + j];
        int row = row0 + r;
        if (row < N) g_h2[row * C + j] = acc * g_norm_src[row];   // norm_src on layer-2 input
    }
}

// ---------------------------------------------------------------- Aggregate layer 2 (into d_out)
__global__ void k_agg2(const int* __restrict__ src, const int* __restrict__ dst,
                       float* __restrict__ out, int E) {
    int gid = blockIdx.x * blockDim.x + threadIdx.x;
    int e = gid / 10;
    if (e >= E) return;
    int c = (gid - e * 10) * 4;
    int s = src[e], d = dst[e];
    float4 v = *(const float4*)&g_h2[s * C + c];
    float* p = &out[d * C + c];
    asm volatile("red.global.add.v4.f32 [%0], {%1,%2,%3,%4};"
                 :: "l"(p), "f"(v.x), "f"(v.y), "f"(v.z), "f"(v.w) : "memory");
}

// ---------------------------------------------------------------- Epilogue 2: (agg2*nd + b2) -> log_softmax, in place
__global__ void k_softmax(float* __restrict__ out, const float* __restrict__ b2, int N) {
    int n = (blockIdx.x * blockDim.x + threadIdx.x) >> 5;
    int lane = threadIdx.x & 31;
    if (n >= N) return;
    float nd = g_norm_dst[n];
    float v0 = fmaf(out[n * C + lane], nd, b2[lane]);
    float v1 = -1e30f;
    if (lane < C - 32) v1 = fmaf(out[n * C + 32 + lane], nd, b2[32 + lane]);
    float m = fmaxf(v0, v1);
    #pragma unroll
    for (int off = 16; off > 0; off >>= 1)
        m = fmaxf(m, __shfl_xor_sync(0xffffffffu, m, off));
    float s = __expf(v0 - m) + ((lane < C - 32) ? __expf(v1 - m) : 0.f);
    #pragma unroll
    for (int off = 16; off > 0; off >>= 1)
        s += __shfl_xor_sync(0xffffffffu, s, off);
    float lse = m + __logf(s);
    out[n * C + lane] = v0 - lse;
    if (lane < C - 32) out[n * C + 32 + lane] = v1 - lse;
}

// ---------------------------------------------------------------- launch
extern "C" void kernel_launch(void* const* d_in, const int* in_sizes, int n_in,
                              void* d_out, int out_size) {
    const float* feat = (const float*)d_in[0];
    const int*   src  = (const int*)d_in[1];
    const int*   dst  = (const int*)d_in[2];
    const float* W1   = (const float*)d_in[3];
    const float* b1   = (const float*)d_in[4];
    const float* W2   = (const float*)d_in[5];
    const float* b2   = (const float*)d_in[6];
    float* out = (float*)d_out;

    const int N = in_sizes[0] / F;
    const int E = in_sizes[1];

    k_zero<<<4096, 256>>>(out, N);
    k_deg<<<(E + 255) / 256, 256>>>(src, dst, E);
    k_norm<<<(N + 255) / 256, 256>>>(N);
    k_gemm1<<<(N + 31) / 32, 256>>>(feat, W1, N);
    {
        long long t = (long long)E * 8;
        k_agg1<<<(int)((t + 255) / 256), 256>>>(src, dst, E);
    }
    k_gemm2<<<(N + 31) / 32, 256>>>(W2, b1, N);
    {
        long long t = (long long)E * 10;
        k_agg2<<<(int)((t + 255) / 256), 256>>>(src, dst, out, E);
    }
    k_softmax<<<(N + 7) / 8, 256>>>(out, b2, N);
}